// round 1
// baseline (speedup 1.0000x reference)
#include <cuda_runtime.h>
#include <cstdint>

// ---------------- problem constants (structure is deterministic) ------------
#define TREES   512
#define TSIZE   400
#define NNODES  (TREES * TSIZE)   // 204800
#define INFEAT  768
#define HFEAT   256
#define G3      768               // 3 * HFEAT
#define MAXLVL  124416            // 243 * 512 (level-5 width)

// level boundaries within a tree: level d = [start[d], start[d+1])
// starts: {0,1,4,13,40,121,364,400}; counts: {1,3,9,27,81,243,36}
// leaves: local node s >= 133

// ---------------- scratch (device bss; no allocation APIs) ------------------
__device__ float g_gx[(size_t)NNODES * G3];   // input-side gates, all nodes
__device__ float g_h [(size_t)NNODES * HFEAT];// hiddens
__device__ float g_gh[(size_t)MAXLVL * G3];   // hidden-side gates, per level

// ---------------- small PTX helpers ----------------------------------------
__device__ __forceinline__ uint32_t f2tf32(float f) {
    uint32_t u;
    asm("cvt.rna.tf32.f32 %0, %1;" : "=r"(u) : "f"(f));
    return u;
}

__device__ __forceinline__ void mma_tf32(float* c, const uint32_t* a, const uint32_t* b) {
    asm volatile(
        "mma.sync.aligned.m16n8k8.row.col.f32.tf32.tf32.f32 "
        "{%0,%1,%2,%3}, {%4,%5,%6,%7}, {%8,%9}, {%0,%1,%2,%3};"
        : "+f"(c[0]), "+f"(c[1]), "+f"(c[2]), "+f"(c[3])
        : "r"(a[0]), "r"(a[1]), "r"(a[2]), "r"(a[3]), "r"(b[0]), "r"(b[1]));
}

__device__ __forceinline__ void cp16(void* smem_dst, const void* gsrc) {
    uint32_t s = (uint32_t)__cvta_generic_to_shared(smem_dst);
    asm volatile("cp.async.cg.shared.global [%0], [%1], 16;" :: "r"(s), "l"(gsrc));
}
__device__ __forceinline__ void cp_commit() { asm volatile("cp.async.commit_group;"); }
template <int N> __device__ __forceinline__ void cp_wait() {
    asm volatile("cp.async.wait_group %0;" :: "n"(N));
}

// ---------------- tf32 GEMM: C[M,768] = A[M,K] * B[768,K]^T + bias ----------
// GATHER=false: A row m = A + m*K              (gx GEMM, K=768)
// GATHER=true : A row m = h[parent(level node m)]  (gh GEMM, K=256)
#define BM 128
#define BN 128
#define BK 32
#define BKP 36   // padded row stride (floats): 4g+tig banks -> conflict-free
#define SMEM_BYTES (2 * (BM * BKP + BN * BKP) * 4)   // 73728

template <int KDIM, bool GATHER>
__global__ void __launch_bounds__(256, 2)
gemm_tf32(const float* __restrict__ A, const float* __restrict__ B,
          const float* __restrict__ bias, float* __restrict__ C,
          int lstart, int lcount)
{
    extern __shared__ float smem[];
    float* sA = smem;                     // 2 stages * BM * BKP
    float* sB = smem + 2 * BM * BKP;      // 2 stages * BN * BKP

    const int lane = threadIdx.x & 31;
    const int warp = threadIdx.x >> 5;
    const int wm = (warp >> 1) * 32;      // warp tile 32(m) x 64(n)
    const int wn = (warp & 1) * 64;
    const int g   = lane >> 2;
    const int tig = lane & 3;

    const int row0 = blockIdx.x * BM;
    const int col0 = blockIdx.y * BN;

    auto load_stage = [&](int buf, int kt) {
        const int k0 = kt * BK;
        #pragma unroll
        for (int i = 0; i < 4; ++i) {              // A: 1024 float4 / 256 thr
            int lin = threadIdx.x + i * 256;
            int r = lin >> 3, cv = lin & 7;
            int m = row0 + r;
            const float* src;
            if (GATHER) {
                int t = m / lcount;
                int s = lstart + (m - t * lcount);
                int par = t * TSIZE + (s - 1) / 3;
                src = A + (size_t)par * KDIM + k0 + cv * 4;
            } else {
                src = A + (size_t)m * KDIM + k0 + cv * 4;
            }
            cp16(&sA[buf * BM * BKP + r * BKP + cv * 4], src);
        }
        #pragma unroll
        for (int i = 0; i < 4; ++i) {              // B: weight rows (out cols)
            int lin = threadIdx.x + i * 256;
            int r = lin >> 3, cv = lin & 7;
            int nidx = col0 + r;
            cp16(&sB[buf * BN * BKP + r * BKP + cv * 4],
                 B + (size_t)nidx * KDIM + k0 + cv * 4);
        }
        cp_commit();
    };

    float acc[2][8][4];
    #pragma unroll
    for (int mi = 0; mi < 2; ++mi)
        #pragma unroll
        for (int ni = 0; ni < 8; ++ni)
            #pragma unroll
            for (int v = 0; v < 4; ++v) acc[mi][ni][v] = 0.f;

    const int KT = KDIM / BK;
    load_stage(0, 0);
    int buf = 0;
    for (int kt = 0; kt < KT; ++kt) {
        if (kt + 1 < KT) { load_stage(buf ^ 1, kt + 1); cp_wait<1>(); }
        else             { cp_wait<0>(); }
        __syncthreads();

        const float* pA = sA + buf * BM * BKP;
        const float* pB = sB + buf * BN * BKP;
        #pragma unroll
        for (int kk = 0; kk < BK / 8; ++kk) {
            const int k0 = kk * 8;
            uint32_t afr[2][4], bfr[8][2];
            #pragma unroll
            for (int mi = 0; mi < 2; ++mi) {
                int r = wm + mi * 16 + g;
                afr[mi][0] = f2tf32(pA[r * BKP + k0 + tig]);
                afr[mi][1] = f2tf32(pA[(r + 8) * BKP + k0 + tig]);
                afr[mi][2] = f2tf32(pA[r * BKP + k0 + tig + 4]);
                afr[mi][3] = f2tf32(pA[(r + 8) * BKP + k0 + tig + 4]);
            }
            #pragma unroll
            for (int ni = 0; ni < 8; ++ni) {
                int c = wn + ni * 8 + g;
                bfr[ni][0] = f2tf32(pB[c * BKP + k0 + tig]);
                bfr[ni][1] = f2tf32(pB[c * BKP + k0 + tig + 4]);
            }
            #pragma unroll
            for (int mi = 0; mi < 2; ++mi)
                #pragma unroll
                for (int ni = 0; ni < 8; ++ni)
                    mma_tf32(acc[mi][ni], afr[mi], bfr[ni]);
        }
        __syncthreads();
        buf ^= 1;
    }

    // epilogue: add bias, store
    #pragma unroll
    for (int mi = 0; mi < 2; ++mi) {
        #pragma unroll
        for (int ni = 0; ni < 8; ++ni) {
            int row = row0 + wm + mi * 16 + g;
            int col = col0 + wn + ni * 8 + 2 * tig;
            float b0 = bias[col], b1 = bias[col + 1];
            float* p0 = C + (size_t)row * G3 + col;
            float* p1 = C + (size_t)(row + 8) * G3 + col;
            p0[0] = acc[mi][ni][0] + b0;
            p0[1] = acc[mi][ni][1] + b1;
            p1[0] = acc[mi][ni][2] + b0;
            p1[1] = acc[mi][ni][3] + b1;
        }
    }
}

// ---------------- elementwise GRU ------------------------------------------
__device__ __forceinline__ float sigmoidf_(float x) {
    return 1.0f / (1.0f + __expf(-x));
}

// level 0: h_parent = 0, gh = b_hh  -> h = (1-z)*n
__global__ void ew_level0(const float* __restrict__ b_hh) {
    int idx = blockIdx.x * blockDim.x + threadIdx.x;   // TREES*HFEAT
    if (idx >= TREES * HFEAT) return;
    int t = idx >> 8, j = idx & 255;
    size_t n = (size_t)t * TSIZE;                       // root node of tree t
    const float* gx = g_gx + n * G3;
    float r = sigmoidf_(gx[j] + b_hh[j]);
    float z = sigmoidf_(gx[HFEAT + j] + b_hh[HFEAT + j]);
    float nn = tanhf(gx[2 * HFEAT + j] + r * b_hh[2 * HFEAT + j]);
    g_h[n * HFEAT + j] = (1.0f - z) * nn;
}

// levels 1..6: uses g_gh written by the gather GEMM for this level
__global__ void ew_level(int lstart, int lcount) {
    int idx = blockIdx.x * blockDim.x + threadIdx.x;   // M*HFEAT
    int M = lcount * TREES;
    if (idx >= M * HFEAT) return;
    int p = idx >> 8, j = idx & 255;
    int t = p / lcount;
    int s = lstart + (p - t * lcount);
    int n   = t * TSIZE + s;
    int par = t * TSIZE + (s - 1) / 3;
    float hp = g_h[(size_t)par * HFEAT + j];
    const float* gx = g_gx + (size_t)n * G3;
    const float* gh = g_gh + (size_t)p * G3;
    float r = sigmoidf_(gx[j] + gh[j]);
    float z = sigmoidf_(gx[HFEAT + j] + gh[HFEAT + j]);
    float nn = tanhf(gx[2 * HFEAT + j] + r * gh[2 * HFEAT + j]);
    g_h[(size_t)n * HFEAT + j] = (1.0f - z) * nn + z * hp;
}

// ---------------- per-tree leaf max (leaves: s in [133, 400)) ---------------
__global__ void leaf_max(float* __restrict__ out) {
    int t = blockIdx.x, j = threadIdx.x;
    const float* base = g_h + (size_t)t * TSIZE * HFEAT;
    float m = -3.402823466e+38f;
    #pragma unroll 4
    for (int s = 133; s < TSIZE; ++s)
        m = fmaxf(m, base[(size_t)s * HFEAT + j]);
    out[(size_t)t * HFEAT + j] = m;
}

// ---------------- launch ----------------------------------------------------
extern "C" void kernel_launch(void* const* d_in, const int* in_sizes, int n_in,
                              void* d_out, int out_size) {
    const float* inputs = (const float*)d_in[0];
    const float* W_ih   = (const float*)d_in[1];
    const float* W_hh   = (const float*)d_in[2];
    const float* b_ih   = (const float*)d_in[3];
    const float* b_hh   = (const float*)d_in[4];
    float* out = (float*)d_out;

    float *p_gx, *p_h, *p_gh;
    cudaGetSymbolAddress((void**)&p_gx, g_gx);
    cudaGetSymbolAddress((void**)&p_h,  g_h);
    cudaGetSymbolAddress((void**)&p_gh, g_gh);

    cudaFuncSetAttribute(gemm_tf32<INFEAT, false>,
                         cudaFuncAttributeMaxDynamicSharedMemorySize, SMEM_BYTES);
    cudaFuncSetAttribute(gemm_tf32<HFEAT, true>,
                         cudaFuncAttributeMaxDynamicSharedMemorySize, SMEM_BYTES);

    // 1) gx = inputs @ W_ih^T + b_ih  for all nodes
    {
        dim3 grid(NNODES / BM, G3 / BN);   // 1600 x 6
        gemm_tf32<INFEAT, false><<<grid, 256, SMEM_BYTES>>>(
            inputs, W_ih, b_ih, p_gx, 0, 1);
    }

    // 2) level 0 (roots): pure elementwise
    ew_level0<<<(TREES * HFEAT + 255) / 256, 256>>>(b_hh);

    // 3) levels 1..6: gather-GEMM gh, then GRU elementwise
    const int lvl_start[7] = {0, 1, 4, 13, 40, 121, 364};
    const int lvl_cnt[7]   = {1, 3, 9, 27, 81, 243, 36};
    for (int d = 1; d < 7; ++d) {
        int M = lvl_cnt[d] * TREES;        // always divisible by 128
        dim3 grid(M / BM, G3 / BN);
        gemm_tf32<HFEAT, true><<<grid, 256, SMEM_BYTES>>>(
            p_h, W_hh, b_hh, p_gh, lvl_start[d], lvl_cnt[d]);
        ew_level<<<(M * HFEAT + 255) / 256, 256>>>(lvl_start[d], lvl_cnt[d]);
    }

    // 4) per-tree max over leaf hiddens
    leaf_max<<<TREES, HFEAT>>>(out);

    (void)in_sizes; (void)n_in; (void)out_size;
}

// round 3
// speedup vs baseline: 1.3251x; 1.3251x over previous
#include <cuda_runtime.h>
#include <cstdint>

// ---------------- problem constants ----------------------------------------
#define TREES   512
#define TSIZE   400
#define NNODES  (TREES * TSIZE)   // 204800
#define INFEAT  768
#define HFEAT   256
#define G3      768

// level geometry (ternary tree, 400 nodes):
//  d:      0    1    2    3     4     5      6
//  cnt:    1    3    9    27    81    243    36
//  start:  0    1    4    13    40    121    364
//  level-major row offsets (rows of HFEAT):
//  off:    0    512  2048 6656  20480 61952  186368
//  parents needed for level d = first PC[d] locals of level d-1:
//  PC:          1    3    9     27    81     12
//  leaves: level-5 locals 12..242 (s=133..363) + all of level 6

// ---------------- scratch (device bss; no allocation APIs) ------------------
__device__ float g_gx  [(size_t)NNODES * G3];          // input gates, node-major
__device__ float g_h   [(size_t)NNODES * HFEAT];       // hiddens, LEVEL-major
__device__ float g_gh  [(size_t)(81 * TREES) * G3];    // parent gates, per level
__device__ float g_wihr[3 * HFEAT * INFEAT];           // tf32-rounded W_ih
__device__ float g_whhr[3 * HFEAT * HFEAT];            // tf32-rounded W_hh

// ---------------- GEMM config -----------------------------------------------
#define BM 128
#define BN 256
#define BK 32
#define NS 4
#define BKP 36                                   // padded row stride (floats)
#define A_STAGE_B (BM * BKP * 4)                 // 18432
#define B_STAGE_B (BN * BKP * 4)                 // 36864
#define STAGE_B   (A_STAGE_B + B_STAGE_B)        // 55296
#define SMEM_TOTAL (NS * STAGE_B)                // 221184

// ---------------- PTX helpers ------------------------------------------------
__device__ __forceinline__ uint32_t f2tf32(float f) {
    uint32_t u; asm("cvt.rna.tf32.f32 %0, %1;" : "=r"(u) : "f"(f)); return u;
}
__device__ __forceinline__ void mma_tf32(float* c, const uint32_t* a, const uint32_t* b) {
    asm volatile(
        "mma.sync.aligned.m16n8k8.row.col.f32.tf32.tf32.f32 "
        "{%0,%1,%2,%3}, {%4,%5,%6,%7}, {%8,%9}, {%0,%1,%2,%3};"
        : "+f"(c[0]), "+f"(c[1]), "+f"(c[2]), "+f"(c[3])
        : "r"(a[0]), "r"(a[1]), "r"(a[2]), "r"(a[3]), "r"(b[0]), "r"(b[1]));
}
__device__ __forceinline__ void cp16(uint32_t saddr, const void* g) {
    asm volatile("cp.async.cg.shared.global [%0], [%1], 16;" :: "r"(saddr), "l"(g));
}
__device__ __forceinline__ void cp_commit() { asm volatile("cp.async.commit_group;"); }

// ---------------- tf32 GEMM: C[M,768] = A[M,KDIM] * B[768,KDIM]^T + bias ----
// B must be pre-rounded to tf32 bit patterns. A is raw fp32 (HW truncates).
// GATHER: logical row r -> A row (r/PC)*STR + r%PC  (parent-subset remap)
template <int KDIM, bool GATHER>
__global__ void __launch_bounds__(256, 1)
gemm_mma(const float* __restrict__ A, const float* __restrict__ B,
         const float* __restrict__ bias, float* __restrict__ C,
         int PC, int STR)
{
    extern __shared__ char smem[];
    const uint32_t sbase = (uint32_t)__cvta_generic_to_shared(smem);
    const int tid  = threadIdx.x;
    const int lane = tid & 31, warp = tid >> 5;
    const int g = lane >> 2, tig = lane & 3;
    const int wm = (warp >> 2) * 64;          // 2 warps along M
    const int wn = (warp & 3) * 64;           // 4 warps along N
    const int col0 = blockIdx.x * BN;
    const int row0 = blockIdx.y * BM;
    const int KT = KDIM / BK;

    // per-thread staging sources / smem offsets (loop-invariant)
    const float* asrc[4]; uint32_t adst[4];
    #pragma unroll
    for (int i = 0; i < 4; ++i) {
        int lin = tid + i * 256, r = lin >> 3, cc = lin & 7;
        int rr = row0 + r, gr;
        if (GATHER) { int t = rr / PC; gr = t * STR + (rr - t * PC); }
        else        { gr = rr; }
        asrc[i] = A + (size_t)gr * KDIM + cc * 4;
        adst[i] = (uint32_t)((r * BKP + cc * 4) * 4);
    }
    const float* bsrc[8]; uint32_t bdst[8];
    #pragma unroll
    for (int i = 0; i < 8; ++i) {
        int lin = tid + i * 256, r = lin >> 3, cc = lin & 7;
        bsrc[i] = B + (size_t)(col0 + r) * KDIM + cc * 4;
        bdst[i] = (uint32_t)((r * BKP + cc * 4) * 4);
    }

    auto issue = [&](int kt) {
        uint32_t sa = sbase + (uint32_t)(kt & (NS - 1)) * STAGE_B;
        uint32_t sb = sa + A_STAGE_B;
        const int ko = kt * BK;
        #pragma unroll
        for (int i = 0; i < 4; ++i) cp16(sa + adst[i], asrc[i] + ko);
        #pragma unroll
        for (int i = 0; i < 8; ++i) cp16(sb + bdst[i], bsrc[i] + ko);
    };

    float acc[4][8][4];
    #pragma unroll
    for (int mi = 0; mi < 4; ++mi)
        #pragma unroll
        for (int ni = 0; ni < 8; ++ni)
            #pragma unroll
            for (int v = 0; v < 4; ++v) acc[mi][ni][v] = 0.f;

    #pragma unroll
    for (int s = 0; s < NS - 1; ++s) { issue(s); cp_commit(); }

    for (int kt = 0; kt < KT; ++kt) {
        asm volatile("cp.async.wait_group %0;" :: "n"(NS - 2));
        __syncthreads();
        int nk = kt + NS - 1;
        if (nk < KT) issue(nk);
        cp_commit();

        const float* sA = (const float*)(smem + (size_t)(kt & (NS - 1)) * STAGE_B);
        const float* sB = (const float*)(smem + (size_t)(kt & (NS - 1)) * STAGE_B + A_STAGE_B);
        #pragma unroll
        for (int kk = 0; kk < BK / 8; ++kk) {
            const int k0 = kk * 8;
            uint32_t afr[4][4], bfr[8][2];
            #pragma unroll
            for (int mi = 0; mi < 4; ++mi) {
                int r = wm + mi * 16 + g;
                afr[mi][0] = __float_as_uint(sA[r * BKP + k0 + tig]);
                afr[mi][1] = __float_as_uint(sA[(r + 8) * BKP + k0 + tig]);
                afr[mi][2] = __float_as_uint(sA[r * BKP + k0 + tig + 4]);
                afr[mi][3] = __float_as_uint(sA[(r + 8) * BKP + k0 + tig + 4]);
            }
            #pragma unroll
            for (int ni = 0; ni < 8; ++ni) {
                int c = wn + ni * 8 + g;
                bfr[ni][0] = __float_as_uint(sB[c * BKP + k0 + tig]);
                bfr[ni][1] = __float_as_uint(sB[c * BKP + k0 + tig + 4]);
            }
            #pragma unroll
            for (int mi = 0; mi < 4; ++mi)
                #pragma unroll
                for (int ni = 0; ni < 8; ++ni)
                    mma_tf32(acc[mi][ni], afr[mi], bfr[ni]);
        }
    }

    // epilogue: add bias (fp32), store
    #pragma unroll
    for (int mi = 0; mi < 4; ++mi) {
        int row = row0 + wm + mi * 16 + g;
        #pragma unroll
        for (int ni = 0; ni < 8; ++ni) {
            int col = col0 + wn + ni * 8 + 2 * tig;
            float b0 = bias[col], b1 = bias[col + 1];
            float2* p0 = (float2*)(C + (size_t)row * G3 + col);
            float2* p1 = (float2*)(C + (size_t)(row + 8) * G3 + col);
            *p0 = make_float2(acc[mi][ni][0] + b0, acc[mi][ni][1] + b1);
            *p1 = make_float2(acc[mi][ni][2] + b0, acc[mi][ni][3] + b1);
        }
    }
}

// ---------------- weight pre-rounding (fp32 -> tf32 bit pattern) ------------
__global__ void round_w(const float* __restrict__ w, float* __restrict__ o, int n) {
    int i = blockIdx.x * 256 + threadIdx.x;
    if (i < n) o[i] = __uint_as_float(f2tf32(w[i]));
}

// ---------------- elementwise GRU -------------------------------------------
__device__ __forceinline__ float sigmoidf_(float x) { return 1.0f / (1.0f + __expf(-x)); }

__global__ void ew_level0(const float* __restrict__ b_hh) {
    int idx = blockIdx.x * blockDim.x + threadIdx.x;     // TREES*HFEAT
    int t = idx >> 8, j = idx & 255;
    const float* gx = g_gx + (size_t)(t * TSIZE) * G3;
    float r = sigmoidf_(gx[j] + b_hh[j]);
    float z = sigmoidf_(gx[HFEAT + j] + b_hh[HFEAT + j]);
    float n = tanhf(gx[2 * HFEAT + j] + r * b_hh[2 * HFEAT + j]);
    g_h[(size_t)t * HFEAT + j] = (1.0f - z) * n;
}

// level d>=1: gh comes from parent-subset GEMM (PC rows per tree)
__global__ void ew_level(int cnt_d, int cnt_p, int start_d, int start_p,
                         int off_d, int off_p, int PC) {
    int idx = blockIdx.x * blockDim.x + threadIdx.x;     // cnt_d*TREES*HFEAT
    int p = idx >> 8, j = idx & 255;
    int t = p / cnt_d;
    int s = start_d + (p - t * cnt_d);
    int lp = (s - 1) / 3 - start_p;                       // parent local idx
    int ghrow = t * PC + lp;
    int hrow  = off_p + t * cnt_p + lp;
    float hp = g_h[(size_t)hrow * HFEAT + j];
    const float* gx = g_gx + (size_t)(t * TSIZE + s) * G3;
    const float* gh = g_gh + (size_t)ghrow * G3;
    float r = sigmoidf_(gx[j] + gh[j]);
    float z = sigmoidf_(gx[HFEAT + j] + gh[HFEAT + j]);
    float n = tanhf(gx[2 * HFEAT + j] + r * gh[2 * HFEAT + j]);
    g_h[(size_t)(off_d + p) * HFEAT + j] = (1.0f - z) * n + z * hp;
}

// ---------------- per-tree leaf max ------------------------------------------
__global__ void leaf_max(float* __restrict__ out) {
    int t = blockIdx.x, j = threadIdx.x;
    float m = -3.402823466e+38f;
    const float* h5 = g_h + (size_t)(61952 + t * 243) * HFEAT;
    #pragma unroll 4
    for (int ls = 12; ls < 243; ++ls) m = fmaxf(m, h5[(size_t)ls * HFEAT + j]);
    const float* h6 = g_h + (size_t)(186368 + t * 36) * HFEAT;
    #pragma unroll 4
    for (int ls = 0; ls < 36; ++ls)   m = fmaxf(m, h6[(size_t)ls * HFEAT + j]);
    out[(size_t)t * HFEAT + j] = m;
}

// ---------------- launch ------------------------------------------------------
extern "C" void kernel_launch(void* const* d_in, const int* in_sizes, int n_in,
                              void* d_out, int out_size) {
    const float* inputs = (const float*)d_in[0];
    const float* W_ih   = (const float*)d_in[1];
    const float* W_hh   = (const float*)d_in[2];
    const float* b_ih   = (const float*)d_in[3];
    const float* b_hh   = (const float*)d_in[4];
    float* out = (float*)d_out;

    float *p_gx, *p_h, *p_gh, *p_wihr, *p_whhr;
    cudaGetSymbolAddress((void**)&p_gx,   g_gx);
    cudaGetSymbolAddress((void**)&p_h,    g_h);
    cudaGetSymbolAddress((void**)&p_gh,   g_gh);
    cudaGetSymbolAddress((void**)&p_wihr, g_wihr);
    cudaGetSymbolAddress((void**)&p_whhr, g_whhr);

    cudaFuncSetAttribute(gemm_mma<INFEAT, false>,
                         cudaFuncAttributeMaxDynamicSharedMemorySize, SMEM_TOTAL);
    cudaFuncSetAttribute(gemm_mma<HFEAT, true>,
                         cudaFuncAttributeMaxDynamicSharedMemorySize, SMEM_TOTAL);

    static const int cnt[7]   = {1, 3, 9, 27, 81, 243, 36};
    static const int start[7] = {0, 1, 4, 13, 40, 121, 364};
    static const int off[7]   = {0, 512, 2048, 6656, 20480, 61952, 186368};
    static const int PC[7]    = {0, 1, 3, 9, 27, 81, 12};

    // 0) pre-round weights to tf32 (rna)
    round_w<<<(3 * HFEAT * INFEAT + 255) / 256, 256>>>(W_ih, p_wihr, 3 * HFEAT * INFEAT);
    round_w<<<(3 * HFEAT * HFEAT + 255) / 256, 256>>>(W_hh, p_whhr, 3 * HFEAT * HFEAT);

    // 1) gx = inputs @ W_ih^T + b_ih   (dense, all nodes)
    gemm_mma<INFEAT, false><<<dim3(G3 / BN, NNODES / BM), 256, SMEM_TOTAL>>>(
        inputs, p_wihr, b_ih, p_gx, 1, 1);

    // 2) roots
    ew_level0<<<TREES, 256>>>(b_hh);

    // 3) levels 1..6: parent-subset gh GEMM + GRU elementwise
    for (int d = 1; d < 7; ++d) {
        int M = PC[d] * TREES;                 // rows = parents needed
        gemm_mma<HFEAT, true><<<dim3(G3 / BN, M / BM), 256, SMEM_TOTAL>>>(
            p_h + (size_t)off[d - 1] * HFEAT, p_whhr, b_hh, p_gh, PC[d], cnt[d - 1]);
        int R = cnt[d] * TREES;
        ew_level<<<R, 256>>>(cnt[d], cnt[d - 1], start[d], start[d - 1],
                             off[d], off[d - 1], PC[d]);
    }

    // 4) leaf max
    leaf_max<<<TREES, 256>>>(out);

    (void)in_sizes; (void)n_in; (void)out_size;
}

// round 4
// speedup vs baseline: 1.8711x; 1.4121x over previous
#include <cuda_runtime.h>
#include <cuda_fp16.h>
#include <cstdint>

// ---------------- problem constants ----------------------------------------
#define TREES   512
#define TSIZE   400
#define NNODES  (TREES * TSIZE)   // 204800
#define INFEAT  768
#define HFEAT   256
#define G3      768

// level geometry (ternary tree, 400 nodes):
//  d:      0    1    2    3     4     5      6
//  cnt:    1    3    9    27    81    243    36
//  start:  0    1    4    13    40    121    364
//  level-major row offsets: 0 512 2048 6656 20480 61952 186368
//  parents for level d = first PC[d] locals of level d-1; PC: 1 3 9 27 81 12
//  leaves: level-5 locals 12..242 + all level-6

// ---------------- scratch (device bss) ---------------------------------------
__device__ float  g_gx [(size_t)NNODES * G3];          // input gates (fp32)
__device__ float  g_h32[(size_t)NNODES * HFEAT];       // hiddens fp32, level-major
__device__ __half g_h16[(size_t)NNODES * HFEAT];       // hiddens fp16, level-major
__device__ float  g_gh [(size_t)(81 * TREES) * G3];    // parent gates per level
__device__ __half g_x16[(size_t)NNODES * INFEAT];      // fp16 inputs
__device__ __half g_wih[3 * HFEAT * INFEAT];           // fp16 W_ih
__device__ __half g_whh[3 * HFEAT * HFEAT];            // fp16 W_hh

// ---------------- GEMM config ------------------------------------------------
#define BM 128
#define BN 256
#define BK 64                                    // halves per stage row (128B)
#define NS 4
#define BKP 72                                   // padded row stride (halves)
#define A_STAGE_B (BM * BKP * 2)                 // 18432
#define B_STAGE_B (BN * BKP * 2)                 // 36864
#define STAGE_B   (A_STAGE_B + B_STAGE_B)        // 55296
#define SMEM_TOTAL (NS * STAGE_B)                // 221184

// ---------------- PTX helpers ------------------------------------------------
__device__ __forceinline__ void mma_f16(float* c, const uint32_t* a, const uint32_t* b) {
    asm volatile(
        "mma.sync.aligned.m16n8k16.row.col.f32.f16.f16.f32 "
        "{%0,%1,%2,%3}, {%4,%5,%6,%7}, {%8,%9}, {%0,%1,%2,%3};"
        : "+f"(c[0]), "+f"(c[1]), "+f"(c[2]), "+f"(c[3])
        : "r"(a[0]), "r"(a[1]), "r"(a[2]), "r"(a[3]), "r"(b[0]), "r"(b[1]));
}
__device__ __forceinline__ void cp16(uint32_t saddr, const void* g) {
    asm volatile("cp.async.cg.shared.global [%0], [%1], 16;" :: "r"(saddr), "l"(g));
}
__device__ __forceinline__ void cp_commit() { asm volatile("cp.async.commit_group;"); }

// ---------------- fp16 GEMM: C[M,768] = A[M,KDIM] * B[768,KDIM]^T + bias -----
// GATHER: logical row r -> A row (r/PC)*STR + r%PC  (parent-subset remap)
template <int KDIM, bool GATHER>
__global__ void __launch_bounds__(256, 1)
gemm_h(const __half* __restrict__ A, const __half* __restrict__ B,
       const float* __restrict__ bias, float* __restrict__ C,
       int PC, int STR)
{
    extern __shared__ char smem[];
    const uint32_t sbase = (uint32_t)__cvta_generic_to_shared(smem);
    const int tid  = threadIdx.x;
    const int lane = tid & 31, warp = tid >> 5;
    const int g = lane >> 2, tig = lane & 3;
    const int wm = (warp >> 2) * 64;          // 2 warps along M
    const int wn = (warp & 3) * 64;           // 4 warps along N
    const int col0 = blockIdx.x * BN;
    const int row0 = blockIdx.y * BM;
    const int KT = KDIM / BK;

    // staging: 16B chunk = 8 halves; A: 128*8=1024 chunks; B: 2048 chunks
    const __half* asrc[4]; uint32_t adst[4];
    #pragma unroll
    for (int i = 0; i < 4; ++i) {
        int lin = tid + i * 256, r = lin >> 3, cc = lin & 7;
        int rr = row0 + r, gr;
        if (GATHER) { int t = rr / PC; gr = t * STR + (rr - t * PC); }
        else        { gr = rr; }
        asrc[i] = A + (size_t)gr * KDIM + cc * 8;
        adst[i] = (uint32_t)((r * BKP + cc * 8) * 2);
    }
    const __half* bsrc[8]; uint32_t bdst[8];
    #pragma unroll
    for (int i = 0; i < 8; ++i) {
        int lin = tid + i * 256, r = lin >> 3, cc = lin & 7;
        bsrc[i] = B + (size_t)(col0 + r) * KDIM + cc * 8;
        bdst[i] = (uint32_t)((r * BKP + cc * 8) * 2);
    }

    auto issue = [&](int kt) {
        uint32_t sa = sbase + (uint32_t)(kt & (NS - 1)) * STAGE_B;
        uint32_t sb = sa + A_STAGE_B;
        const int ko = kt * BK;
        #pragma unroll
        for (int i = 0; i < 4; ++i) cp16(sa + adst[i], asrc[i] + ko);
        #pragma unroll
        for (int i = 0; i < 8; ++i) cp16(sb + bdst[i], bsrc[i] + ko);
    };

    float acc[4][8][4];
    #pragma unroll
    for (int mi = 0; mi < 4; ++mi)
        #pragma unroll
        for (int ni = 0; ni < 8; ++ni)
            #pragma unroll
            for (int v = 0; v < 4; ++v) acc[mi][ni][v] = 0.f;

    #pragma unroll
    for (int s = 0; s < NS - 1; ++s) { issue(s); cp_commit(); }

    for (int kt = 0; kt < KT; ++kt) {
        asm volatile("cp.async.wait_group %0;" :: "n"(NS - 2));
        __syncthreads();
        int nk = kt + NS - 1;
        if (nk < KT) issue(nk);
        cp_commit();

        const __half* sA = (const __half*)(smem + (size_t)(kt & (NS - 1)) * STAGE_B);
        const __half* sB = (const __half*)(smem + (size_t)(kt & (NS - 1)) * STAGE_B + A_STAGE_B);
        #pragma unroll
        for (int kk = 0; kk < BK / 16; ++kk) {           // k16 per step
            const int k0 = kk * 16;
            uint32_t afr[4][4], bfr[8][2];
            #pragma unroll
            for (int mi = 0; mi < 4; ++mi) {
                int r = wm + mi * 16 + g;
                afr[mi][0] = *(const uint32_t*)(sA + r * BKP + k0 + 2 * tig);
                afr[mi][1] = *(const uint32_t*)(sA + (r + 8) * BKP + k0 + 2 * tig);
                afr[mi][2] = *(const uint32_t*)(sA + r * BKP + k0 + 8 + 2 * tig);
                afr[mi][3] = *(const uint32_t*)(sA + (r + 8) * BKP + k0 + 8 + 2 * tig);
            }
            #pragma unroll
            for (int ni = 0; ni < 8; ++ni) {
                int c = wn + ni * 8 + g;
                bfr[ni][0] = *(const uint32_t*)(sB + c * BKP + k0 + 2 * tig);
                bfr[ni][1] = *(const uint32_t*)(sB + c * BKP + k0 + 8 + 2 * tig);
            }
            #pragma unroll
            for (int mi = 0; mi < 4; ++mi)
                #pragma unroll
                for (int ni = 0; ni < 8; ++ni)
                    mma_f16(acc[mi][ni], afr[mi], bfr[ni]);
        }
    }

    // epilogue: add bias (fp32), store
    #pragma unroll
    for (int mi = 0; mi < 4; ++mi) {
        int row = row0 + wm + mi * 16 + g;
        #pragma unroll
        for (int ni = 0; ni < 8; ++ni) {
            int col = col0 + wn + ni * 8 + 2 * tig;
            float b0 = bias[col], b1 = bias[col + 1];
            float2* p0 = (float2*)(C + (size_t)row * G3 + col);
            float2* p1 = (float2*)(C + (size_t)(row + 8) * G3 + col);
            *p0 = make_float2(acc[mi][ni][0] + b0, acc[mi][ni][1] + b1);
            *p1 = make_float2(acc[mi][ni][2] + b0, acc[mi][ni][3] + b1);
        }
    }
}

// ---------------- fp32 -> fp16 conversion (8 elems/thread) -------------------
__global__ void f2h(const float* __restrict__ in, __half* __restrict__ out, int n8) {
    int i = blockIdx.x * 256 + threadIdx.x;
    if (i >= n8) return;
    const float4* p = (const float4*)in + i * 2;
    float4 v0 = p[0], v1 = p[1];
    __half2 h0 = __floats2half2_rn(v0.x, v0.y);
    __half2 h1 = __floats2half2_rn(v0.z, v0.w);
    __half2 h2 = __floats2half2_rn(v1.x, v1.y);
    __half2 h3 = __floats2half2_rn(v1.z, v1.w);
    uint4 u;
    u.x = *(uint32_t*)&h0; u.y = *(uint32_t*)&h1;
    u.z = *(uint32_t*)&h2; u.w = *(uint32_t*)&h3;
    *((uint4*)out + i) = u;
}

// ---------------- elementwise GRU --------------------------------------------
__device__ __forceinline__ float sigmoidf_(float x) { return 1.0f / (1.0f + __expf(-x)); }

__global__ void ew_level0(const float* __restrict__ b_hh) {
    int idx = blockIdx.x * blockDim.x + threadIdx.x;     // TREES*HFEAT
    int t = idx >> 8, j = idx & 255;
    const float* gx = g_gx + (size_t)(t * TSIZE) * G3;
    float r = sigmoidf_(gx[j] + b_hh[j]);
    float z = sigmoidf_(gx[HFEAT + j] + b_hh[HFEAT + j]);
    float n = tanhf(gx[2 * HFEAT + j] + r * b_hh[2 * HFEAT + j]);
    float h = (1.0f - z) * n;
    g_h32[(size_t)t * HFEAT + j] = h;
    g_h16[(size_t)t * HFEAT + j] = __float2half_rn(h);
}

// level d>=1: gh from parent-subset GEMM (PC rows per tree)
__global__ void ew_level(int cnt_d, int cnt_p, int start_d, int start_p,
                         int off_d, int off_p, int PC) {
    int idx = blockIdx.x * blockDim.x + threadIdx.x;     // cnt_d*TREES*HFEAT
    int p = idx >> 8, j = idx & 255;
    int t = p / cnt_d;
    int s = start_d + (p - t * cnt_d);
    int lp = (s - 1) / 3 - start_p;                       // parent local idx
    int ghrow = t * PC + lp;
    int hrow  = off_p + t * cnt_p + lp;
    float hp = g_h32[(size_t)hrow * HFEAT + j];
    const float* gx = g_gx + (size_t)(t * TSIZE + s) * G3;
    const float* gh = g_gh + (size_t)ghrow * G3;
    float r = sigmoidf_(gx[j] + gh[j]);
    float z = sigmoidf_(gx[HFEAT + j] + gh[HFEAT + j]);
    float n = tanhf(gx[2 * HFEAT + j] + r * gh[2 * HFEAT + j]);
    float h = (1.0f - z) * n + z * hp;
    g_h32[(size_t)(off_d + p) * HFEAT + j] = h;
    g_h16[(size_t)(off_d + p) * HFEAT + j] = __float2half_rn(h);
}

// ---------------- per-tree leaf max -------------------------------------------
__global__ void leaf_max(float* __restrict__ out) {
    int t = blockIdx.x, j = threadIdx.x;
    float m = -3.402823466e+38f;
    const float* h5 = g_h32 + (size_t)(61952 + t * 243) * HFEAT;
    #pragma unroll 4
    for (int ls = 12; ls < 243; ++ls) m = fmaxf(m, h5[(size_t)ls * HFEAT + j]);
    const float* h6 = g_h32 + (size_t)(186368 + t * 36) * HFEAT;
    #pragma unroll 4
    for (int ls = 0; ls < 36; ++ls)   m = fmaxf(m, h6[(size_t)ls * HFEAT + j]);
    out[(size_t)t * HFEAT + j] = m;
}

// ---------------- launch -------------------------------------------------------
extern "C" void kernel_launch(void* const* d_in, const int* in_sizes, int n_in,
                              void* d_out, int out_size) {
    const float* inputs = (const float*)d_in[0];
    const float* W_ih   = (const float*)d_in[1];
    const float* W_hh   = (const float*)d_in[2];
    const float* b_ih   = (const float*)d_in[3];
    const float* b_hh   = (const float*)d_in[4];
    float* out = (float*)d_out;

    float *p_gx, *p_gh;
    __half *p_x16, *p_wih, *p_whh, *p_h16;
    cudaGetSymbolAddress((void**)&p_gx,  g_gx);
    cudaGetSymbolAddress((void**)&p_gh,  g_gh);
    cudaGetSymbolAddress((void**)&p_x16, g_x16);
    cudaGetSymbolAddress((void**)&p_wih, g_wih);
    cudaGetSymbolAddress((void**)&p_whh, g_whh);
    cudaGetSymbolAddress((void**)&p_h16, g_h16);

    cudaFuncSetAttribute(gemm_h<INFEAT, false>,
                         cudaFuncAttributeMaxDynamicSharedMemorySize, SMEM_TOTAL);
    cudaFuncSetAttribute(gemm_h<HFEAT, true>,
                         cudaFuncAttributeMaxDynamicSharedMemorySize, SMEM_TOTAL);

    static const int cnt[7]   = {1, 3, 9, 27, 81, 243, 36};
    static const int start[7] = {0, 1, 4, 13, 40, 121, 364};
    static const int off[7]   = {0, 512, 2048, 6656, 20480, 61952, 186368};
    static const int PC[7]    = {0, 1, 3, 9, 27, 81, 12};

    // 0) fp16 conversions
    f2h<<<(NNODES * INFEAT / 8 + 255) / 256, 256>>>(inputs, p_x16, NNODES * INFEAT / 8);
    f2h<<<(3 * HFEAT * INFEAT / 8 + 255) / 256, 256>>>(W_ih, p_wih, 3 * HFEAT * INFEAT / 8);
    f2h<<<(3 * HFEAT * HFEAT / 8 + 255) / 256, 256>>>(W_hh, p_whh, 3 * HFEAT * HFEAT / 8);

    // 1) gx = inputs @ W_ih^T + b_ih   (dense, all nodes)
    gemm_h<INFEAT, false><<<dim3(G3 / BN, NNODES / BM), 256, SMEM_TOTAL>>>(
        p_x16, p_wih, b_ih, p_gx, 1, 1);

    // 2) roots
    ew_level0<<<TREES, 256>>>(b_hh);

    // 3) levels 1..6: parent-subset gh GEMM + GRU elementwise
    for (int d = 1; d < 7; ++d) {
        int M = PC[d] * TREES;                 // rows = parents needed
        gemm_h<HFEAT, true><<<dim3(G3 / BN, M / BM), 256, SMEM_TOTAL>>>(
            p_h16 + (size_t)off[d - 1] * HFEAT, p_whh, b_hh, p_gh, PC[d], cnt[d - 1]);
        int R = cnt[d] * TREES;
        ew_level<<<R, 256>>>(cnt[d], cnt[d - 1], start[d], start[d - 1],
                             off[d], off[d - 1], PC[d]);
    }

    // 4) leaf max
    leaf_max<<<TREES, 256>>>(out);

    (void)in_sizes; (void)n_in; (void)out_size;
}

// round 5
// speedup vs baseline: 1.9542x; 1.0444x over previous
#include <cuda_runtime.h>
#include <cuda_fp16.h>
#include <cstdint>

// ---------------- problem constants ----------------------------------------
#define TREES   512
#define TSIZE   400
#define NNODES  (TREES * TSIZE)   // 204800
#define INFEAT  768
#define HFEAT   256
#define G3      768

// level geometry (ternary tree, 400 nodes):
//  d:      0    1    2    3     4     5      6
//  cnt:    1    3    9    27    81    243    36
//  start:  0    1    4    13    40    121    364
//  level-major row offsets: 0 512 2048 6656 20480 61952 186368
//  parents for level d = first PC[d] locals of level d-1; PC: 1 3 9 27 81 12
//  leaves: level-5 locals 12..242 + all level-6

// ---------------- scratch (device bss) ---------------------------------------
__device__ float  g_gx [(size_t)NNODES * G3];          // input gates (fp32)
__device__ float  g_h32[(size_t)NNODES * HFEAT];       // hiddens fp32, level-major
__device__ __half g_h16[(size_t)NNODES * HFEAT];       // hiddens fp16, level-major
__device__ float  g_gh [(size_t)(81 * TREES) * G3];    // parent gates per level
__device__ __half g_x16[(size_t)NNODES * INFEAT];      // fp16 inputs
__device__ __half g_wih[3 * HFEAT * INFEAT];           // fp16 W_ih
__device__ __half g_whh[3 * HFEAT * HFEAT];            // fp16 W_hh

// ---------------- GEMM config ------------------------------------------------
#define BM 128
#define BN 256
#define BK 64                                    // halves per stage row
#define NS 4
#define BKP 72                                   // padded row stride (halves)
#define A_STAGE_B (BM * BKP * 2)                 // 18432
#define B_STAGE_B (BN * BKP * 2)                 // 36864
#define STAGE_B   (A_STAGE_B + B_STAGE_B)        // 55296
#define SMEM_TOTAL (NS * STAGE_B)                // 221184
#define NTHR 512

// ---------------- PTX helpers ------------------------------------------------
__device__ __forceinline__ void mma_f16(float* c, const uint32_t* a, const uint32_t* b) {
    asm volatile(
        "mma.sync.aligned.m16n8k16.row.col.f32.f16.f16.f32 "
        "{%0,%1,%2,%3}, {%4,%5,%6,%7}, {%8,%9}, {%0,%1,%2,%3};"
        : "+f"(c[0]), "+f"(c[1]), "+f"(c[2]), "+f"(c[3])
        : "r"(a[0]), "r"(a[1]), "r"(a[2]), "r"(a[3]), "r"(b[0]), "r"(b[1]));
}
__device__ __forceinline__ void ldsm4(uint32_t* r, uint32_t saddr) {
    asm volatile("ldmatrix.sync.aligned.m8n8.x4.shared.b16 {%0,%1,%2,%3}, [%4];"
        : "=r"(r[0]), "=r"(r[1]), "=r"(r[2]), "=r"(r[3]) : "r"(saddr));
}
__device__ __forceinline__ void cp16(uint32_t saddr, const void* g) {
    asm volatile("cp.async.cg.shared.global [%0], [%1], 16;" :: "r"(saddr), "l"(g));
}
__device__ __forceinline__ void cp_commit() { asm volatile("cp.async.commit_group;"); }

// ---------------- fp16 GEMM: C[M,768] = A[M,KDIM] * B[768,KDIM]^T + bias -----
// GATHER: logical row r -> A row (r/PC)*STR + r%PC  (parent-subset remap)
template <int KDIM, bool GATHER>
__global__ void __launch_bounds__(NTHR, 1)
gemm_h(const __half* __restrict__ A, const __half* __restrict__ B,
       const float* __restrict__ bias, float* __restrict__ C,
       int PC, int STR)
{
    extern __shared__ char smem[];
    const uint32_t sbase = (uint32_t)__cvta_generic_to_shared(smem);
    const int tid  = threadIdx.x;
    const int lane = tid & 31, warp = tid >> 5;
    const int wm = (warp >> 3) * 64;          // 2 warp-groups along M
    const int wn = (warp & 7) * 32;           // 8 along N
    const int col0 = blockIdx.x * BN;
    const int row0 = blockIdx.y * BM;
    const int KT = KDIM / BK;

    // --- staging (16B chunks): A 1024 chunks, B 2048 chunks, 512 threads ----
    const __half* asrc[2]; uint32_t adst[2];
    #pragma unroll
    for (int i = 0; i < 2; ++i) {
        int lin = tid + i * NTHR, r = lin >> 3, cc = lin & 7;
        int rr = row0 + r, gr;
        if (GATHER) { int t = rr / PC; gr = t * STR + (rr - t * PC); }
        else        { gr = rr; }
        asrc[i] = A + (size_t)gr * KDIM + cc * 8;
        adst[i] = (uint32_t)((r * BKP + cc * 8) * 2);
    }
    const __half* bsrc[4]; uint32_t bdst[4];
    #pragma unroll
    for (int i = 0; i < 4; ++i) {
        int lin = tid + i * NTHR, r = lin >> 3, cc = lin & 7;
        bsrc[i] = B + (size_t)(col0 + r) * KDIM + cc * 8;
        bdst[i] = (uint32_t)((r * BKP + cc * 8) * 2);
    }
    auto issue = [&](int kt) {
        uint32_t sa = sbase + (uint32_t)(kt & (NS - 1)) * STAGE_B;
        uint32_t sb = sa + A_STAGE_B;
        const int ko = kt * BK;
        #pragma unroll
        for (int i = 0; i < 2; ++i) cp16(sa + adst[i], asrc[i] + ko);
        #pragma unroll
        for (int i = 0; i < 4; ++i) cp16(sb + bdst[i], bsrc[i] + ko);
    };

    // --- ldmatrix per-lane byte offsets (within stage) -----------------------
    // A tile mi: matrices (m0-7,k0)(m8-15,k0)(m0-7,k8)(m8-15,k8)
    const int j = lane >> 3, sub = lane & 7;
    uint32_t aoff[4], boff[2];
    #pragma unroll
    for (int mi = 0; mi < 4; ++mi) {
        int arow = wm + mi * 16 + (j & 1) * 8 + sub;
        aoff[mi] = (uint32_t)(arow * BKP * 2 + (j >> 1) * 16);
    }
    // B pair p: matrices (n0-7,k0)(n0-7,k8)(n8-15,k0)(n8-15,k8)
    #pragma unroll
    for (int p = 0; p < 2; ++p) {
        int brow = wn + p * 16 + ((lane >> 4) & 1) * 8 + sub;
        boff[p] = (uint32_t)(brow * BKP * 2 + ((lane >> 3) & 1) * 16);
    }

    float acc[4][4][4];
    #pragma unroll
    for (int mi = 0; mi < 4; ++mi)
        #pragma unroll
        for (int ni = 0; ni < 4; ++ni)
            #pragma unroll
            for (int v = 0; v < 4; ++v) acc[mi][ni][v] = 0.f;

    #pragma unroll
    for (int s = 0; s < NS - 1; ++s) { issue(s); cp_commit(); }

    for (int kt = 0; kt < KT; ++kt) {
        asm volatile("cp.async.wait_group %0;" :: "n"(NS - 2));
        __syncthreads();
        int nk = kt + NS - 1;
        if (nk < KT) issue(nk);
        cp_commit();

        uint32_t sA = sbase + (uint32_t)(kt & (NS - 1)) * STAGE_B;
        uint32_t sB = sA + A_STAGE_B;
        #pragma unroll
        for (int kk = 0; kk < BK / 16; ++kk) {
            const uint32_t kb = kk * 32;              // 16 halves = 32 bytes
            uint32_t afr[4][4], bfr[2][4];
            #pragma unroll
            for (int mi = 0; mi < 4; ++mi) ldsm4(afr[mi], sA + aoff[mi] + kb);
            #pragma unroll
            for (int p = 0; p < 2; ++p)   ldsm4(bfr[p], sB + boff[p] + kb);
            #pragma unroll
            for (int mi = 0; mi < 4; ++mi) {
                #pragma unroll
                for (int p = 0; p < 2; ++p) {
                    mma_f16(acc[mi][2 * p],     afr[mi], &bfr[p][0]);
                    mma_f16(acc[mi][2 * p + 1], afr[mi], &bfr[p][2]);
                }
            }
        }
    }

    // epilogue: add bias (fp32), store
    const int g = lane >> 2, tig = lane & 3;
    #pragma unroll
    for (int mi = 0; mi < 4; ++mi) {
        int row = row0 + wm + mi * 16 + g;
        #pragma unroll
        for (int ni = 0; ni < 4; ++ni) {
            int col = col0 + wn + ni * 8 + 2 * tig;
            float b0 = bias[col], b1 = bias[col + 1];
            float2* p0 = (float2*)(C + (size_t)row * G3 + col);
            float2* p1 = (float2*)(C + (size_t)(row + 8) * G3 + col);
            *p0 = make_float2(acc[mi][ni][0] + b0, acc[mi][ni][1] + b1);
            *p1 = make_float2(acc[mi][ni][2] + b0, acc[mi][ni][3] + b1);
        }
    }
}

// ---------------- fp32 -> fp16 conversion (8 elems/thread) -------------------
__global__ void f2h(const float* __restrict__ in, __half* __restrict__ out, int n8) {
    int i = blockIdx.x * 256 + threadIdx.x;
    if (i >= n8) return;
    const float4* p = (const float4*)in + i * 2;
    float4 v0 = p[0], v1 = p[1];
    __half2 h0 = __floats2half2_rn(v0.x, v0.y);
    __half2 h1 = __floats2half2_rn(v0.z, v0.w);
    __half2 h2 = __floats2half2_rn(v1.x, v1.y);
    __half2 h3 = __floats2half2_rn(v1.z, v1.w);
    uint4 u;
    u.x = *(uint32_t*)&h0; u.y = *(uint32_t*)&h1;
    u.z = *(uint32_t*)&h2; u.w = *(uint32_t*)&h3;
    *((uint4*)out + i) = u;
}

// ---------------- elementwise GRU --------------------------------------------
__device__ __forceinline__ float sigmoidf_(float x) { return 1.0f / (1.0f + __expf(-x)); }

__global__ void ew_level0(const float* __restrict__ b_hh) {
    int idx = blockIdx.x * blockDim.x + threadIdx.x;     // TREES*HFEAT
    int t = idx >> 8, j = idx & 255;
    const float* gx = g_gx + (size_t)(t * TSIZE) * G3;
    float r = sigmoidf_(gx[j] + b_hh[j]);
    float z = sigmoidf_(gx[HFEAT + j] + b_hh[HFEAT + j]);
    float n = tanhf(gx[2 * HFEAT + j] + r * b_hh[2 * HFEAT + j]);
    float h = (1.0f - z) * n;
    g_h32[(size_t)t * HFEAT + j] = h;
    g_h16[(size_t)t * HFEAT + j] = __float2half_rn(h);
}

// level d>=1: gh from parent-subset GEMM (PC rows per tree)
__global__ void ew_level(int cnt_d, int cnt_p, int start_d, int start_p,
                         int off_d, int off_p, int PC) {
    int idx = blockIdx.x * blockDim.x + threadIdx.x;     // cnt_d*TREES*HFEAT
    int p = idx >> 8, j = idx & 255;
    int t = p / cnt_d;
    int s = start_d + (p - t * cnt_d);
    int lp = (s - 1) / 3 - start_p;                       // parent local idx
    int ghrow = t * PC + lp;
    int hrow  = off_p + t * cnt_p + lp;
    float hp = g_h32[(size_t)hrow * HFEAT + j];
    const float* gx = g_gx + (size_t)(t * TSIZE + s) * G3;
    const float* gh = g_gh + (size_t)ghrow * G3;
    float r = sigmoidf_(gx[j] + gh[j]);
    float z = sigmoidf_(gx[HFEAT + j] + gh[HFEAT + j]);
    float n = tanhf(gx[2 * HFEAT + j] + r * gh[2 * HFEAT + j]);
    float h = (1.0f - z) * n + z * hp;
    g_h32[(size_t)(off_d + p) * HFEAT + j] = h;
    g_h16[(size_t)(off_d + p) * HFEAT + j] = __float2half_rn(h);
}

// ---------------- per-tree leaf max -------------------------------------------
__global__ void leaf_max(float* __restrict__ out) {
    int t = blockIdx.x, j = threadIdx.x;
    float m = -3.402823466e+38f;
    const float* h5 = g_h32 + (size_t)(61952 + t * 243) * HFEAT;
    #pragma unroll 4
    for (int ls = 12; ls < 243; ++ls) m = fmaxf(m, h5[(size_t)ls * HFEAT + j]);
    const float* h6 = g_h32 + (size_t)(186368 + t * 36) * HFEAT;
    #pragma unroll 4
    for (int ls = 0; ls < 36; ++ls)   m = fmaxf(m, h6[(size_t)ls * HFEAT + j]);
    out[(size_t)t * HFEAT + j] = m;
}

// ---------------- launch -------------------------------------------------------
extern "C" void kernel_launch(void* const* d_in, const int* in_sizes, int n_in,
                              void* d_out, int out_size) {
    const float* inputs = (const float*)d_in[0];
    const float* W_ih   = (const float*)d_in[1];
    const float* W_hh   = (const float*)d_in[2];
    const float* b_ih   = (const float*)d_in[3];
    const float* b_hh   = (const float*)d_in[4];
    float* out = (float*)d_out;

    float *p_gx, *p_gh;
    __half *p_x16, *p_wih, *p_whh, *p_h16;
    cudaGetSymbolAddress((void**)&p_gx,  g_gx);
    cudaGetSymbolAddress((void**)&p_gh,  g_gh);
    cudaGetSymbolAddress((void**)&p_x16, g_x16);
    cudaGetSymbolAddress((void**)&p_wih, g_wih);
    cudaGetSymbolAddress((void**)&p_whh, g_whh);
    cudaGetSymbolAddress((void**)&p_h16, g_h16);

    cudaFuncSetAttribute(gemm_h<INFEAT, false>,
                         cudaFuncAttributeMaxDynamicSharedMemorySize, SMEM_TOTAL);
    cudaFuncSetAttribute(gemm_h<HFEAT, true>,
                         cudaFuncAttributeMaxDynamicSharedMemorySize, SMEM_TOTAL);

    static const int cnt[7]   = {1, 3, 9, 27, 81, 243, 36};
    static const int start[7] = {0, 1, 4, 13, 40, 121, 364};
    static const int off[7]   = {0, 512, 2048, 6656, 20480, 61952, 186368};
    static const int PC[7]    = {0, 1, 3, 9, 27, 81, 12};

    // 0) fp16 conversions
    f2h<<<(NNODES * INFEAT / 8 + 255) / 256, 256>>>(inputs, p_x16, NNODES * INFEAT / 8);
    f2h<<<(3 * HFEAT * INFEAT / 8 + 255) / 256, 256>>>(W_ih, p_wih, 3 * HFEAT * INFEAT / 8);
    f2h<<<(3 * HFEAT * HFEAT / 8 + 255) / 256, 256>>>(W_hh, p_whh, 3 * HFEAT * HFEAT / 8);

    // 1) gx = inputs @ W_ih^T + b_ih   (dense, all nodes)
    gemm_h<INFEAT, false><<<dim3(G3 / BN, NNODES / BM), NTHR, SMEM_TOTAL>>>(
        p_x16, p_wih, b_ih, p_gx, 1, 1);

    // 2) roots
    ew_level0<<<TREES, 256>>>(b_hh);

    // 3) levels 1..6: parent-subset gh GEMM + GRU elementwise
    for (int d = 1; d < 7; ++d) {
        int M = PC[d] * TREES;                 // rows = parents needed
        gemm_h<HFEAT, true><<<dim3(G3 / BN, M / BM), NTHR, SMEM_TOTAL>>>(
            p_h16 + (size_t)off[d - 1] * HFEAT, p_whh, b_hh, p_gh, PC[d], cnt[d - 1]);
        int R = cnt[d] * TREES;
        ew_level<<<R, 256>>>(cnt[d], cnt[d - 1], start[d], start[d - 1],
                             off[d], off[d - 1], PC[d]);
    }

    // 4) leaf max
    leaf_max<<<TREES, 256>>>(out);

    (void)in_sizes; (void)n_in; (void)out_size;
}